// round 5
// baseline (speedup 1.0000x reference)
#include <cuda_runtime.h>
#include <cstdint>

// Input:  x  (4, 64, 512, 512) fp32 -> flatten (BC=256, 512, 512)
// Output: [ll | lh | hl | hh], each (256, 256, 256) fp32, concatenated.
//
// R5: persistent grid-stride version of the R1 shape. 2048 CTAs x 256 thr;
// each thread processes 16 pair-units, software-pipelined 2 at a time so 4
// independent LDG.128 are in flight per iteration. No wave transitions.

static constexpr int BC    = 256;
static constexpr int H_OUT = 256;
static constexpr int W_OUT = 256;
static constexpr int PLANE = BC * H_OUT * W_OUT;   // 16,777,216 floats/plane
static constexpr int W4    = 128;                  // float4 per input row
static constexpr unsigned TOTAL_PAIRS = 8388608u;  // BC*H_OUT*(W_OUT/2)
static constexpr int THREADS = 256;
static constexpr int BLOCKS  = 2048;
static constexpr unsigned STRIDE = (unsigned)THREADS * BLOCKS;  // 524288
static constexpr int ITERS = TOTAL_PAIRS / STRIDE;              // 16 (exact)

__device__ __forceinline__ float4 ldcs4(const float4* p) {
    float4 v;
    asm volatile("ld.global.cs.v4.f32 {%0,%1,%2,%3}, [%4];"
                 : "=f"(v.x), "=f"(v.y), "=f"(v.z), "=f"(v.w) : "l"(p));
    return v;
}
__device__ __forceinline__ void stcs2(float* p, float2 v) {
    asm volatile("st.global.cs.v2.f32 [%0], {%1,%2};"
                 :: "l"(p), "f"(v.x), "f"(v.y) : "memory");
}

// idx -> (input float4 index of row0, output float offset within plane)
__device__ __forceinline__ void decode(unsigned idx, unsigned& in_q, unsigned& out_o) {
    unsigned wq = idx & (W4 - 1);
    unsigned t  = idx >> 7;
    unsigned ho = t & (H_OUT - 1);
    unsigned bc = t >> 8;
    in_q  = (bc * 512u + 2u * ho) * W4 + wq;
    out_o = (bc * H_OUT + ho) * W_OUT + 2u * wq;
}

__device__ __forceinline__ void haar2(const float4 r0, const float4 r1,
                                      float2& ll, float2& lh, float2& hl, float2& hh) {
    {
        float apb = r0.x + r0.y, amb = r0.x - r0.y;
        float cpd = r1.x + r1.y, cmd = r1.x - r1.y;
        ll.x = (apb + cpd) * 0.5f;  lh.x = (apb - cpd) * 0.5f;
        hl.x = (amb + cmd) * 0.5f;  hh.x = (amb - cmd) * 0.5f;
    }
    {
        float apb = r0.z + r0.w, amb = r0.z - r0.w;
        float cpd = r1.z + r1.w, cmd = r1.z - r1.w;
        ll.y = (apb + cpd) * 0.5f;  lh.y = (apb - cpd) * 0.5f;
        hl.y = (amb + cmd) * 0.5f;  hh.y = (amb - cmd) * 0.5f;
    }
}

__global__ void __launch_bounds__(THREADS) fast_dwt_kernel(
    const float4* __restrict__ x,
    float* __restrict__ out)
{
    unsigned base = blockIdx.x * (unsigned)THREADS + threadIdx.x;

    #pragma unroll
    for (int it = 0; it < ITERS; it += 2) {
        unsigned idx0 = base + (unsigned)it * STRIDE;
        unsigned idx1 = idx0 + STRIDE;

        unsigned q0, o0, q1, o1;
        decode(idx0, q0, o0);
        decode(idx1, q1, o1);

        // 4 independent 16B loads in flight
        float4 a0 = ldcs4(x + q0);
        float4 b0 = ldcs4(x + q0 + W4);
        float4 a1 = ldcs4(x + q1);
        float4 b1 = ldcs4(x + q1 + W4);

        float2 ll, lh, hl, hh;
        haar2(a0, b0, ll, lh, hl, hh);
        stcs2(out + 0u * PLANE + o0, ll);
        stcs2(out + 1u * PLANE + o0, lh);
        stcs2(out + 2u * PLANE + o0, hl);
        stcs2(out + 3u * PLANE + o0, hh);

        haar2(a1, b1, ll, lh, hl, hh);
        stcs2(out + 0u * PLANE + o1, ll);
        stcs2(out + 1u * PLANE + o1, lh);
        stcs2(out + 2u * PLANE + o1, hl);
        stcs2(out + 3u * PLANE + o1, hh);
    }
}

extern "C" void kernel_launch(void* const* d_in, const int* in_sizes, int n_in,
                              void* d_out, int out_size)
{
    const float4* x = (const float4*)d_in[0];
    float* out = (float*)d_out;
    fast_dwt_kernel<<<BLOCKS, THREADS>>>(x, out);
}

// round 6
// speedup vs baseline: 1.0309x; 1.0309x over previous
#include <cuda_runtime.h>
#include <cstdint>

// Input:  x  (4, 64, 512, 512) fp32 -> flatten (BC=256, 512, 512)
// Output: [ll | lh | hl | hh], each (256, 256, 256) fp32, concatenated.
//
// Final: thin-thread shape (best measured). Each thread reads one float4
// from rows 2h and 2h+1 (two 2x2 Haar blocks), writes a float2 to each of
// the 4 output planes. Exact grid (no tail branch), power-of-two index math.
// Kernel is at the sm_103a LTS ceiling (~6300 B/cyc path-independent):
// 512 MiB total traffic / ~6.45 TB/s ≈ 75 us kernel time.

static constexpr int BC    = 256;
static constexpr int H_OUT = 256;
static constexpr int W_OUT = 256;
static constexpr int PLANE = BC * H_OUT * W_OUT;   // 16,777,216 floats/plane
static constexpr int W4    = 128;                  // float4 per input row
static constexpr long long TOTAL_PAIRS = (long long)BC * H_OUT * (W_OUT / 2); // 8,388,608

__device__ __forceinline__ void stcs2(float* p, float2 v) {
    asm volatile("st.global.cs.v2.f32 [%0], {%1,%2};"
                 :: "l"(p), "f"(v.x), "f"(v.y) : "memory");
}

__global__ void __launch_bounds__(256) fast_dwt_kernel(
    const float4* __restrict__ x,
    float* __restrict__ out)
{
    // Exact grid: 8,388,608 threads, no bounds check.
    unsigned idx = blockIdx.x * blockDim.x + threadIdx.x;

    unsigned wq = idx & (W4 - 1);          // quad within row
    unsigned t  = idx >> 7;
    unsigned ho = t & (H_OUT - 1);
    unsigned bc = t >> 8;

    unsigned row0 = (bc * 512u + 2u * ho) * W4;
    float4 r0 = __ldg(x + row0 + wq);
    float4 r1 = __ldg(x + row0 + W4 + wq);

    float2 ll, lh, hl, hh;
    {
        float apb = r0.x + r0.y, amb = r0.x - r0.y;
        float cpd = r1.x + r1.y, cmd = r1.x - r1.y;
        ll.x = (apb + cpd) * 0.5f;  lh.x = (apb - cpd) * 0.5f;
        hl.x = (amb + cmd) * 0.5f;  hh.x = (amb - cmd) * 0.5f;
    }
    {
        float apb = r0.z + r0.w, amb = r0.z - r0.w;
        float cpd = r1.z + r1.w, cmd = r1.z - r1.w;
        ll.y = (apb + cpd) * 0.5f;  lh.y = (apb - cpd) * 0.5f;
        hl.y = (amb + cmd) * 0.5f;  hh.y = (amb - cmd) * 0.5f;
    }

    unsigned o = (bc * H_OUT + ho) * W_OUT + 2u * wq;
    stcs2(out + 0u * PLANE + o, ll);
    stcs2(out + 1u * PLANE + o, lh);
    stcs2(out + 2u * PLANE + o, hl);
    stcs2(out + 3u * PLANE + o, hh);
}

extern "C" void kernel_launch(void* const* d_in, const int* in_sizes, int n_in,
                              void* d_out, int out_size)
{
    const float4* x = (const float4*)d_in[0];
    float* out = (float*)d_out;

    const int threads = 256;
    const int blocks = (int)(TOTAL_PAIRS / threads);   // 32768, exact
    fast_dwt_kernel<<<blocks, threads>>>(x, out);
}